// round 17
// baseline (speedup 1.0000x reference)
#include <cuda_runtime.h>
#include <cuda_fp16.h>
#include <stdint.h>

#define N_NODES 16384
#define CIN     128
#define HC      256
#define OUTC    128
#define E_EDGES 196608
#define DHW     8192
#define BATCH   2
#define NEG_ACT 0.01f
#define CSR_CAP 64

typedef unsigned long long ull;

// ---- scratch (device globals; no allocation allowed) ----
__device__ __align__(16) float  g_h[N_NODES * HC];        // 16 MB fp32
__device__ __align__(16) float  g_pre[N_NODES * OUTC];    // 8 MB
__device__ __align__(16) uint2  g_wp[8192];               // W permuted fp16 (64 KB)
__device__ __align__(8)  float2 g_u[N_NODES];             // per-node a.h (2 heads)
__device__ int    g_fill[N_NODES];
__device__ int    g_csr[N_NODES * CSR_CAP];               // padded CSR (4 MB)
__device__ double g_sum[OUTC];
__device__ double g_sq[OUTC];

#define FMA2(d, a, b, c) \
    asm("fma.rn.f32x2 %0, %1, %2, %3;" : "=l"(d) : "l"(a), "l"(b), "l"(c))
#define ADD2(d, a, b) \
    asm("add.rn.f32x2 %0, %1, %2;" : "=l"(d) : "l"(a), "l"(b))
#define PACK2(d, lo, hi) \
    asm("mov.b64 %0, {%1,%2};" : "=l"(d) : "f"(lo), "f"(hi))
#define UNPK(lo, hi, v) \
    asm("mov.b64 {%0,%1}, %2;" : "=f"(lo), "=f"(hi) : "l"(v))
#define ABSM 0x7FFFFFFF7FFFFFFFull

// ------- K0: zero fill / BN sums + permute W to fp16 B-fragments ---------
__global__ void k_prep(const float* __restrict__ w) {
    int i = blockIdx.x * blockDim.x + threadIdx.x;
    if (i < N_NODES) g_fill[i] = 0;
    if (i < OUTC) { g_sum[i] = 0.0; g_sq[i] = 0.0; }
    if (i < 8192) {
        int lane = i & 31, t = i >> 5;       // t = nt*8 + kt (256 tiles)
        int kt = t & 7, nt = t >> 3;
        int k0 = kt * 16, nn = nt * 8 + (lane >> 2);
        int kk = k0 + 2 * (lane & 3);
        __half2 r0 = __floats2half2_rn(w[kk * HC + nn],       w[(kk + 1) * HC + nn]);
        __half2 r1 = __floats2half2_rn(w[(kk + 8) * HC + nn], w[(kk + 9) * HC + nn]);
        uint2 r;
        r.x = *(uint32_t*)&r0;
        r.y = *(uint32_t*)&r1;
        g_wp[t * 32 + lane] = r;
    }
}

// ------- K1: h = xf @ W + b via HMMA + per-node u = a.h (fp32 h out) -----
__global__ void k_gemm(const float* __restrict__ x,
                       const float* __restrict__ bias,
                       const float* __restrict__ att) {
    __shared__ __align__(16) __half As[32 * 136];   // 32 nodes x 128 k, pad 8
    int tid = threadIdx.x;
    int wid = tid >> 5, lane = tid & 31;
    int n0b = blockIdx.x * 32;
    int b   = n0b >> 13, s0 = n0b & 8191;

    {
        int m = tid & 31, kbase = tid >> 5;
        #pragma unroll
        for (int i = 0; i < 16; i++) {
            int k = kbase + i * 8;
            As[m * 136 + k] = __float2half_rn(x[((size_t)b * CIN + k) * DHW + s0 + m]);
        }
    }
    __syncthreads();

    int warp_n0 = wid * 32;
    int tq = lane >> 2, tr = lane & 3;
    float c[2][4][4];
    #pragma unroll
    for (int mt = 0; mt < 2; mt++)
        #pragma unroll
        for (int j = 0; j < 4; j++)
            #pragma unroll
            for (int r = 0; r < 4; r++) c[mt][j][r] = 0.f;

    #pragma unroll
    for (int kt = 0; kt < 8; kt++) {
        int k0 = kt * 16;
        uint32_t a[2][4];
        #pragma unroll
        for (int mt = 0; mt < 2; mt++) {
            const __half* base = As + (mt * 16 + tq) * 136 + k0 + 2 * tr;
            a[mt][0] = *(const uint32_t*)(base);
            a[mt][1] = *(const uint32_t*)(base + 8 * 136);
            a[mt][2] = *(const uint32_t*)(base + 8);
            a[mt][3] = *(const uint32_t*)(base + 8 * 136 + 8);
        }
        #pragma unroll
        for (int j = 0; j < 4; j++) {
            int ntg = (warp_n0 >> 3) + j;
            uint2 bb = __ldg(&g_wp[(ntg * 8 + kt) * 32 + lane]);
            #pragma unroll
            for (int mt = 0; mt < 2; mt++) {
                asm("mma.sync.aligned.m16n8k16.row.col.f32.f16.f16.f32 "
                    "{%0,%1,%2,%3}, {%4,%5,%6,%7}, {%8,%9}, {%0,%1,%2,%3};"
                    : "+f"(c[mt][j][0]), "+f"(c[mt][j][1]),
                      "+f"(c[mt][j][2]), "+f"(c[mt][j][3])
                    : "r"(a[mt][0]), "r"(a[mt][1]), "r"(a[mt][2]), "r"(a[mt][3]),
                      "r"(bb.x), "r"(bb.y));
            }
        }
    }

    // epilogue: +bias, store fp32 h, accumulate u-partials
    float pu[2][2] = {{0.f, 0.f}, {0.f, 0.f}};
    #pragma unroll
    for (int mt = 0; mt < 2; mt++) {
        int m0 = mt * 16 + tq;
        #pragma unroll
        for (int j = 0; j < 4; j++) {
            int n = warp_n0 + j * 8 + 2 * tr;
            float b0 = __ldg(&bias[n]), b1 = __ldg(&bias[n + 1]);
            float a0 = __ldg(&att[n]),  a1 = __ldg(&att[n + 1]);
            float v00 = c[mt][j][0] + b0, v01 = c[mt][j][1] + b1;
            float v10 = c[mt][j][2] + b0, v11 = c[mt][j][3] + b1;
            pu[mt][0] += a0 * v00 + a1 * v01;
            pu[mt][1] += a0 * v10 + a1 * v11;
            *(float2*)&g_h[(size_t)(n0b + m0) * HC + n]     = make_float2(v00, v01);
            *(float2*)&g_h[(size_t)(n0b + m0 + 8) * HC + n] = make_float2(v10, v11);
        }
    }
    #pragma unroll
    for (int mt = 0; mt < 2; mt++)
        #pragma unroll
        for (int r = 0; r < 2; r++) {
            pu[mt][r] += __shfl_xor_sync(0xffffffffu, pu[mt][r], 1);
            pu[mt][r] += __shfl_xor_sync(0xffffffffu, pu[mt][r], 2);
        }
    __syncthreads();
    float* su = (float*)As;
    if (tr == 0) {
        #pragma unroll
        for (int mt = 0; mt < 2; mt++) {
            su[(mt * 16 + tq)     * 8 + wid] = pu[mt][0];
            su[(mt * 16 + tq + 8) * 8 + wid] = pu[mt][1];
        }
    }
    __syncthreads();
    if (tid < 32) {
        float u0 = su[tid * 8 + 0] + su[tid * 8 + 1] + su[tid * 8 + 2] + su[tid * 8 + 3];
        float u1 = su[tid * 8 + 4] + su[tid * 8 + 5] + su[tid * 8 + 6] + su[tid * 8 + 7];
        g_u[n0b + tid] = make_float2(u0, u1);
    }
}

// ------- K2: scatter edges directly into padded CSR ----------------------
__global__ void k_scatter(const int* __restrict__ ei) {
    int e = blockIdx.x * blockDim.x + threadIdx.x;
    if (e < E_EDGES) {
        unsigned d = (unsigned)ei[E_EDGES + e];
        unsigned s = (unsigned)ei[e];
        if (d < N_NODES && s < N_NODES) {
            int pos = atomicAdd(&g_fill[d], 1);
            if (pos < CSR_CAP) g_csr[d * CSR_CAP + pos] = (int)s;
        }
    }
}

// ---------------- K3: per-node GATv2, packed f32x2 math ------------------
__device__ __forceinline__ void ld_row2(int node, int lane, ull* r) {
    const ulonglong2* hp = (const ulonglong2*)g_h;   // 64 ulonglong2 per row
    ulonglong2 v0 = __ldg(&hp[(size_t)node * 64 + lane * 2]);
    ulonglong2 v1 = __ldg(&hp[(size_t)node * 64 + lane * 2 + 1]);
    r[0] = v0.x; r[1] = v0.y; r[2] = v1.x; r[3] = v1.y;
}

// partial score: Sum over lane's 8 channels of a'_c * |hs_c + hd_c|
__device__ __forceinline__ float score_part(const ull* s2, const ull* d2, const ull* a2) {
    ull sc = 0ull;
    #pragma unroll
    for (int k = 0; k < 4; k++) {
        ull t;
        ADD2(t, s2[k], d2[k]);
        t &= ABSM;
        FMA2(sc, t, a2[k], sc);
    }
    float lo, hi;
    UNPK(lo, hi, sc);
    return lo + hi;
}

__device__ __forceinline__ float red16(float s) {
    s += __shfl_xor_sync(0xffffffffu, s, 8);
    s += __shfl_xor_sync(0xffffffffu, s, 4);
    s += __shfl_xor_sync(0xffffffffu, s, 2);
    s += __shfl_xor_sync(0xffffffffu, s, 1);
    return s;
}

__global__ void k_attn(const float* __restrict__ att,
                       const float* __restrict__ gat_bias) {
    int warp = (blockIdx.x * blockDim.x + threadIdx.x) >> 5;
    int lane = threadIdx.x & 31;
    if (warp >= N_NODES) return;
    int i = warp;

    ull hd2[4];
    ld_row2(i, lane, hd2);
    const float4* ap = (const float4*)att;
    float4 A0 = __ldg(&ap[lane * 2]);
    float4 A1 = __ldg(&ap[lane * 2 + 1]);
    ull at2[4];
    PACK2(at2[0], 0.4f * A0.x, 0.4f * A0.y);
    PACK2(at2[1], 0.4f * A0.z, 0.4f * A0.w);
    PACK2(at2[2], 0.4f * A1.x, 0.4f * A1.y);
    PACK2(at2[3], 0.4f * A1.z, 0.4f * A1.w);

    float2 ud = __ldg(&g_u[i]);
    float uh_d = (lane < 16) ? ud.x : ud.y;
    float base_d = 0.6f * uh_d;

    // self loop
    float p0 = __expf(red16(score_part(hd2, hd2, at2)) + 1.2f * uh_d);
    ull acc2[4], p02;
    PACK2(p02, p0, p0);
    float den = p0;
    #pragma unroll
    for (int k = 0; k < 4; k++) { ull z = 0ull; FMA2(acc2[k], hd2[k], p02, z); }

    int start = i * CSR_CAP;
    int deg   = g_fill[i];
    if (deg > CSR_CAP) deg = CSR_CAP;
    int j = 0;
    for (; j + 2 <= deg; j += 2) {
        int srcA = __ldg(&g_csr[start + j]);
        int srcB = __ldg(&g_csr[start + j + 1]);
        ull a2r[4], b2r[4];
        ld_row2(srcA, lane, a2r);
        ld_row2(srcB, lane, b2r);
        float2 uA = __ldg(&g_u[srcA]);
        float2 uB = __ldg(&g_u[srcB]);
        float uhA = (lane < 16) ? uA.x : uA.y;
        float uhB = (lane < 16) ? uB.x : uB.y;
        float sA = red16(score_part(a2r, hd2, at2)) + 0.6f * uhA + base_d;
        float sB = red16(score_part(b2r, hd2, at2)) + 0.6f * uhB + base_d;
        float pA = __expf(sA);
        float pB = __expf(sB);
        den += pA + pB;
        ull pA2, pB2;
        PACK2(pA2, pA, pA);
        PACK2(pB2, pB, pB);
        #pragma unroll
        for (int k = 0; k < 4; k++) {
            FMA2(acc2[k], a2r[k], pA2, acc2[k]);
            FMA2(acc2[k], b2r[k], pB2, acc2[k]);
        }
    }
    if (j < deg) {
        int src = __ldg(&g_csr[start + j]);
        ull s2r[4];
        ld_row2(src, lane, s2r);
        float2 uS = __ldg(&g_u[src]);
        float uhS = (lane < 16) ? uS.x : uS.y;
        float p = __expf(red16(score_part(s2r, hd2, at2)) + 0.6f * uhS + base_d);
        den += p;
        ull p2;
        PACK2(p2, p, p);
        #pragma unroll
        for (int k = 0; k < 4; k++) FMA2(acc2[k], s2r[k], p2, acc2[k]);
    }

    float inv = 1.0f / den;
    float q[8];
    #pragma unroll
    for (int k = 0; k < 4; k++) UNPK(q[2 * k], q[2 * k + 1], acc2[k]);
    #pragma unroll
    for (int k = 0; k < 8; k++) q[k] *= inv;
    float o[8];
    #pragma unroll
    for (int k = 0; k < 8; k++) o[k] = __shfl_xor_sync(0xffffffffu, q[k], 16);

    if (lane < 16) {
        int c0 = lane * 8;
        float4 r0, r1;
        r0.x = 0.5f * (q[0] + o[0]) + __ldg(&gat_bias[c0 + 0]);
        r0.y = 0.5f * (q[1] + o[1]) + __ldg(&gat_bias[c0 + 1]);
        r0.z = 0.5f * (q[2] + o[2]) + __ldg(&gat_bias[c0 + 2]);
        r0.w = 0.5f * (q[3] + o[3]) + __ldg(&gat_bias[c0 + 3]);
        r1.x = 0.5f * (q[4] + o[4]) + __ldg(&gat_bias[c0 + 4]);
        r1.y = 0.5f * (q[5] + o[5]) + __ldg(&gat_bias[c0 + 5]);
        r1.z = 0.5f * (q[6] + o[6]) + __ldg(&gat_bias[c0 + 6]);
        r1.w = 0.5f * (q[7] + o[7]) + __ldg(&gat_bias[c0 + 7]);
        float4* op = (float4*)g_pre;
        op[(size_t)i * 32 + lane * 2]     = r0;
        op[(size_t)i * 32 + lane * 2 + 1] = r1;
    }
}

// ---------------- K4: BN statistics ----------------
__global__ void k_bnstats() {
    __shared__ float ssum[256], ssq[256];
    int c = threadIdx.x & 127;
    int g = threadIdx.x >> 7;
    int rbase = blockIdx.x * 128;
    float sum = 0.f, sq = 0.f;
    for (int r = rbase + g; r < rbase + 128; r += 2) {
        float v = g_pre[(size_t)r * 128 + c];
        sum += v; sq += v * v;
    }
    ssum[threadIdx.x] = sum;
    ssq[threadIdx.x]  = sq;
    __syncthreads();
    if (g == 0) {
        double S = (double)ssum[c] + (double)ssum[c + 128];
        double Q = (double)ssq[c]  + (double)ssq[c + 128];
        atomicAdd(&g_sum[c], S);
        atomicAdd(&g_sq[c], Q);
    }
}

// ------- K5: BN fold + apply + LeakyReLU + transpose (32x32 tiles) -------
__global__ void k_final(const float* __restrict__ gamma,
                        const float* __restrict__ beta,
                        float* __restrict__ out) {
    __shared__ float t[32][33];
    __shared__ float ssc[32], ssh[32];
    int c0 = blockIdx.y * 32;
    int s0 = blockIdx.x * 32;
    int b  = blockIdx.z;
    int x = threadIdx.x;
    int y = threadIdx.y;

    if (y == 0) {
        int c = c0 + x;
        double mean = g_sum[c] / (double)N_NODES;
        double var  = g_sq[c] / (double)N_NODES - mean * mean;
        float inv = (float)(1.0 / sqrt(var + 1e-5));
        float a = gamma[c] * inv;
        ssc[x] = a;
        ssh[x] = beta[c] - (float)mean * a;
    }

    #pragma unroll
    for (int i = y; i < 32; i += 8)
        t[i][x] = g_pre[(size_t)(b * DHW + s0 + i) * 128 + c0 + x];
    __syncthreads();

    #pragma unroll
    for (int i = y; i < 32; i += 8) {
        float v = t[x][i] * ssc[i] + ssh[i];
        out[((size_t)b * OUTC + c0 + i) * DHW + s0 + x] = fmaxf(v, NEG_ACT * v);
    }
}

// ---------------- launch ----------------
extern "C" void kernel_launch(void* const* d_in, const int* in_sizes, int n_in,
                              void* d_out, int out_size) {
    const float* x        = (const float*)d_in[0];
    const int*   ei       = (const int*)d_in[1];     // int64 downcast to int32
    const float* lin_w    = (const float*)d_in[2];
    const float* lin_b    = (const float*)d_in[3];
    const float* att      = (const float*)d_in[4];
    const float* gat_bias = (const float*)d_in[5];
    const float* bn_gamma = (const float*)d_in[6];
    const float* bn_beta  = (const float*)d_in[7];
    float*       out      = (float*)d_out;

    k_prep<<<N_NODES / 256, 256>>>(lin_w);
    k_gemm<<<N_NODES / 32, 256>>>(x, lin_b, att);
    k_scatter<<<(E_EDGES + 255) / 256, 256>>>(ei);
    k_attn<<<(N_NODES * 32) / 128, 128>>>(att, gat_bias);
    k_bnstats<<<N_NODES / 128, 256>>>();
    dim3 ftb(32, 8);
    dim3 fgr(DHW / 32, OUTC / 32, BATCH);
    k_final<<<fgr, ftb>>>(bn_gamma, bn_beta, out);
}